// round 16
// baseline (speedup 1.0000x reference)
#include <cuda_runtime.h>
#include <cuda_fp16.h>

#define Bn 8
#define Tn 1024
#define IND 512
#define NH 8
#define HD 64
#define OUTD 512
#define MAXPOS 512

// -------- scratch (allocations forbidden; device globals) --------
__device__ __half g_xh [(size_t)Bn*Tn*IND];
__device__ __half g_wqh[(size_t)OUTD*IND];        // [n][k]
__device__ __half g_wkvh[(size_t)2*OUTD*IND];     // [n][k]
__device__ __half g_wouth[(size_t)IND*OUTD];      // [n][k]
__device__ __half g_relh[(size_t)(2*MAXPOS+1)*HD];
__device__ __half g_qh[(size_t)Bn*NH*Tn*HD];
__device__ __half g_kh[(size_t)Bn*NH*Tn*HD];
__device__ __half g_vh[(size_t)Bn*NH*Tn*HD];
__device__ __half g_atth[(size_t)Bn*Tn*OUTD];

// -------- helpers --------
__device__ __forceinline__ void mma16(float* c,
    unsigned a0, unsigned a1, unsigned a2, unsigned a3,
    unsigned b0, unsigned b1)
{
    asm volatile(
      "mma.sync.aligned.m16n8k16.row.col.f32.f16.f16.f32 "
      "{%0,%1,%2,%3},{%4,%5,%6,%7},{%8,%9},{%0,%1,%2,%3};"
      : "+f"(c[0]), "+f"(c[1]), "+f"(c[2]), "+f"(c[3])
      : "r"(a0), "r"(a1), "r"(a2), "r"(a3), "r"(b0), "r"(b1));
}
__device__ __forceinline__ void cpa8(unsigned dst, const void* src) {
    asm volatile("cp.async.ca.shared.global [%0], [%1], 8;" :: "r"(dst), "l"(src));
}
__device__ __forceinline__ void cpa16(unsigned dst, const void* src) {
    asm volatile("cp.async.cg.shared.global [%0], [%1], 16;" :: "r"(dst), "l"(src));
}
__device__ __forceinline__ void cpa_commit() { asm volatile("cp.async.commit_group;"); }
__device__ __forceinline__ void ldsm4(unsigned &r0, unsigned &r1, unsigned &r2, unsigned &r3,
                                      unsigned addr)
{
    asm volatile("ldmatrix.sync.aligned.m8n8.x4.shared.b16 {%0,%1,%2,%3}, [%4];"
        : "=r"(r0), "=r"(r1), "=r"(r2), "=r"(r3) : "r"(addr));
}
__device__ __forceinline__ void ldsm4t(unsigned &r0, unsigned &r1, unsigned &r2, unsigned &r3,
                                       unsigned addr)
{
    asm volatile("ldmatrix.sync.aligned.m8n8.x4.trans.shared.b16 {%0,%1,%2,%3}, [%4];"
        : "=r"(r0), "=r"(r1), "=r"(r2), "=r"(r3) : "r"(addr));
}
__device__ __forceinline__ float ex2f(float x) {
    float r; asm("ex2.approx.ftz.f32 %0, %1;" : "=f"(r) : "f"(x)); return r;
}
__device__ __forceinline__ unsigned h2u(float a, float b) {
    __half2 h = __floats2half2_rn(a, b);
    return *(unsigned*)&h;
}
#define EXSC 0.1803368809f
#define EXBI (-5.7707801636f)

// ============================================================
// conversion: flat blocks (x, rel) + tiled transpose blocks (W).
// ============================================================
#define NX (Bn*Tn*IND/4)
#define NR ((2*MAXPOS+1)*HD/4)
#define FLATB ((NX + NR + 255)/256)
#define TQ 64
#define TKV 128
#define TO 64
__global__ void conv_all(const float* __restrict__ x, const float* __restrict__ rel,
                         const float* __restrict__ Wq, const float* __restrict__ Wkv,
                         const float* __restrict__ Wout)
{
    const int b = blockIdx.x;
    const int t = threadIdx.x;
    if (b < FLATB) {
        int i = b*256 + t;
        if (i < NX) {
            float4 v = *(const float4*)(x + 4*(size_t)i);
            *(__half2*)(g_xh + 4*(size_t)i)     = __floats2half2_rn(v.x, v.y);
            *(__half2*)(g_xh + 4*(size_t)i + 2) = __floats2half2_rn(v.z, v.w);
        } else if (i < NX + NR) {
            int j = i - NX;
            float4 v = *(const float4*)(rel + 4*(size_t)j);
            *(__half2*)(g_relh + 4*(size_t)j)     = __floats2half2_rn(v.x, v.y);
            *(__half2*)(g_relh + 4*(size_t)j + 2) = __floats2half2_rn(v.z, v.w);
        }
        return;
    }
    int tb = b - FLATB;
    const float* src; __half* dst; int N, ncols_t;
    if (tb < TQ)            { src = Wq;   dst = g_wqh;   N = 512;  ncols_t = 8;  }
    else if (tb < TQ+TKV)   { tb -= TQ;   src = Wkv;  dst = g_wkvh;  N = 1024; ncols_t = 16; }
    else                    { tb -= TQ+TKV; src = Wout; dst = g_wouth; N = 512; ncols_t = 8; }
    const int k0 = (tb / ncols_t) * 64;
    const int n0 = (tb % ncols_t) * 64;

    __shared__ float s[64][65];
    {
        int r = t >> 2, cq = t & 3;
        const float* rp = src + (size_t)(k0 + r)*N + n0;
#pragma unroll
        for (int j = 0; j < 4; j++) {
            float4 v = *(const float4*)(rp + (cq + j*4)*4);
            s[r][(cq + j*4)*4 + 0] = v.x;
            s[r][(cq + j*4)*4 + 1] = v.y;
            s[r][(cq + j*4)*4 + 2] = v.z;
            s[r][(cq + j*4)*4 + 3] = v.w;
        }
    }
    __syncthreads();
    {
        int n = t >> 2, ks = (t & 3) * 16;
        __half* wp = dst + (size_t)(n0 + n)*512 + k0 + ks;
        __half hv[16];
#pragma unroll
        for (int j = 0; j < 16; j++)
            hv[j] = __float2half_rn(s[ks + j][n]);
        *(uint4*)(wp)     = *(uint4*)(hv);
        *(uint4*)(wp + 8) = *(uint4*)(hv + 8);
    }
}
#define NCONVB (FLATB + TQ + TKV + TO)

// ============================================================
// fp16 GEMM body: BM=128, BN=64, BK=32, 256 thr (8 warps, 32x32
// warp tiles), THREE-stage cp.async pipeline, ONE barrier/iter.
// smem = 3*(128+64)*40 halfs = 46,080 B -> 3 blocks/SM.
// ============================================================
#define LDS_S 40
#define GSA_BYTES (128*LDS_S*2)
#define GSB_BYTES (64*LDS_S*2)
#define GEMM_SMEM (3*(GSA_BYTES + GSB_BYTES))

#define GSTAGE(bufi, kn, APTR, LDA, BPTR)                                       \
    {                                                                           \
        const unsigned ao = (unsigned)(bufi) * GSA_BYTES;                       \
        const unsigned bo = (unsigned)(bufi) * GSB_BYTES;                       \
        _Pragma("unroll")                                                       \
        for (int j = 0; j < 4; j++) {                                           \
            int c = tid + j*256, row = c >> 3, c4 = (c & 7) << 2;               \
            cpa8(sa_u + ao + row*(LDS_S*2) + c4*2,                              \
                 (APTR) + (size_t)(row0 + row)*(LDA) + (kn) + c4);              \
        }                                                                       \
        _Pragma("unroll")                                                       \
        for (int j = 0; j < 2; j++) {                                           \
            int c = tid + j*256, n = c >> 3, c4 = (c & 7) << 2;                 \
            cpa8(sb_u + bo + n*(LDS_S*2) + c4*2,                                \
                 (BPTR) + (size_t)n*IND + (kn) + c4);                           \
        }                                                                       \
        cpa_commit();                                                           \
    }

#define HGEMM(APTR, LDA, BPTR)                                                  \
    extern __shared__ __half smg[];                                             \
    __half* s_a = smg;                                                          \
    __half* s_b = smg + 3*128*LDS_S;                                            \
    const int tid = threadIdx.x, lane = tid & 31, warp = tid >> 5;              \
    const int wr = warp >> 1, wc = warp & 1;                                    \
    const int lq = lane >> 2, lr = lane & 3;                                    \
    const int rsel = (lane & 7) + ((lane >> 3) & 1)*8;                          \
    const int csel = (lane >> 4)*8;                                             \
    unsigned sa_u = (unsigned)__cvta_generic_to_shared(s_a);                    \
    unsigned sb_u = (unsigned)__cvta_generic_to_shared(s_b);                    \
    float acc[2][4][4];                                                         \
    _Pragma("unroll") for (int i = 0; i < 2; i++)                               \
    _Pragma("unroll") for (int j = 0; j < 4; j++)                               \
    _Pragma("unroll") for (int e = 0; e < 4; e++) acc[i][j][e] = 0.f;           \
    GSTAGE(0, 0,  APTR, LDA, BPTR)                                              \
    GSTAGE(1, 32, APTR, LDA, BPTR)                                              \
    int bufc = 0, bufs = 2;                                                     \
    for (int it = 0; it < 16; it++) {                                           \
        if (it < 15) asm volatile("cp.async.wait_group 1;");                    \
        else         asm volatile("cp.async.wait_group 0;");                    \
        __syncthreads();                                                        \
        if (it < 14) GSTAGE(bufs, (it+2) << 5, APTR, LDA, BPTR)                 \
        const unsigned pa_u = sa_u + (unsigned)bufc*GSA_BYTES;                  \
        const unsigned pb_u = sb_u + (unsigned)bufc*GSB_BYTES;                  \
        _Pragma("unroll")                                                       \
        for (int ks = 0; ks < 2; ks++) {                                        \
            unsigned a[2][4];                                                   \
            _Pragma("unroll")                                                   \
            for (int rt = 0; rt < 2; rt++)                                      \
                ldsm4(a[rt][0], a[rt][1], a[rt][2], a[rt][3],                   \
                      pa_u + (unsigned)((wr*32 + rt*16 + rsel)*LDS_S            \
                                        + ks*16 + csel)*2);                     \
            _Pragma("unroll")                                                   \
            for (int cp = 0; cp < 2; cp++) {                                    \
                unsigned b0, b1, b2, b3;                                        \
                ldsm4(b0, b1, b2, b3,                                           \
                      pb_u + (unsigned)((wc*32 + cp*16 + rsel)*LDS_S            \
                                        + ks*16 + csel)*2);                     \
                _Pragma("unroll")                                               \
                for (int rt = 0; rt < 2; rt++) {                                \
                    mma16(acc[rt][2*cp  ], a[rt][0],a[rt][1],a[rt][2],a[rt][3], \
                          b0, b2);                                              \
                    mma16(acc[rt][2*cp+1], a[rt][0],a[rt][1],a[rt][2],a[rt][3], \
                          b1, b3);                                              \
                }                                                               \
            }                                                                   \
        }                                                                       \
        bufc = (bufc == 2) ? 0 : bufc + 1;                                      \
        bufs = (bufs == 2) ? 0 : bufs + 1;                                      \
    }

// ============================================================
// Kernel 1: QKV projection (fp16).  BN=64: one head per tile.
// ============================================================
__global__ __launch_bounds__(256) void qkv_mma(
    const float* __restrict__ bq, const float* __restrict__ bkv)
{
    const int row0 = blockIdx.y * 128, col0 = blockIdx.x * 64;
    const __half* Bp; const float* bias;
    if (col0 < OUTD) { Bp = g_wqh  + (size_t)col0*IND;         bias = bq  + col0; }
    else             { Bp = g_wkvh + (size_t)(col0-OUTD)*IND;  bias = bkv + (col0-OUTD); }

    HGEMM(g_xh, IND, Bp)

    const int seg = col0 >> 9;
    const int h   = (col0 & 511) >> 6;
    __half* dst = (seg == 0) ? g_qh : (seg == 1) ? g_kh : g_vh;

#pragma unroll
    for (int rt = 0; rt < 2; rt++)
#pragma unroll
        for (int ct = 0; ct < 4; ct++)
#pragma unroll
            for (int hh = 0; hh < 2; hh++) {
                int r  = row0 + wr*32 + rt*16 + lq + 8*hh;
                int bb = r >> 10, tt = r & 1023;
                int col = wc*32 + ct*8 + 2*lr;
                __half2 w = __floats2half2_rn(acc[rt][ct][2*hh+0] + bias[col],
                                              acc[rt][ct][2*hh+1] + bias[col+1]);
                *(__half2*)(dst + ((size_t)(bb*NH + h)*Tn + tt)*HD + col) = w;
            }
}

// ============================================================
// Kernel 3: output projection (fp16 -> fp32 out)
// ============================================================
__global__ __launch_bounds__(256) void out_mma(
    const float* __restrict__ bout, float* __restrict__ out)
{
    const int row0 = blockIdx.y * 128, col0 = blockIdx.x * 64;
    const __half* Bp = g_wouth + (size_t)col0*OUTD;

    HGEMM(g_atth, OUTD, Bp)

#pragma unroll
    for (int rt = 0; rt < 2; rt++)
#pragma unroll
        for (int ct = 0; ct < 4; ct++)
#pragma unroll
            for (int hh = 0; hh < 2; hh++) {
                int r   = row0 + wr*32 + rt*16 + lq + 8*hh;
                int col = wc*32 + ct*8 + 2*lr;
                float2 w;
                w.x = acc[rt][ct][2*hh+0] + bout[col0 + col];
                w.y = acc[rt][ct][2*hh+1] + bout[col0 + col+1];
                *(float2*)(out + (size_t)r * IND + col0 + col) = w;
            }
}

// ============================================================
// Kernel 2: attention — unchanged from committed R14/R15.
// ============================================================
#define LDH 72
#define RELR 192
#define LPSH 88
#define OFF_V   9216
#define OFF_REL 18432
#define OFF_SCR 32256
#define ATTN_SMEM (37888*2)     // 75,776 B

__global__ __launch_bounds__(128, 3) void attn_mma()
{
    extern __shared__ __half smh[];
    const int tid = threadIdx.x, lane = tid & 31, warp = tid >> 5;
    const int lq = lane >> 2, lr = lane & 3;
    const int bx = blockIdx.x;
    const int ntile = (bx & 1) ? (7 - (bx >> 1)) : (8 + (bx >> 1));
    const int n0 = ntile * 64;
    const int bh = blockIdx.y;
    const size_t base = (size_t)bh * Tn * HD;

    const unsigned smb = (unsigned)__cvta_generic_to_shared(smh);
    const unsigned u_kb[2] = { smb, smb + 64*LDH*2 };
    const unsigned u_vb[2] = { smb + OFF_V*2, smb + (OFF_V + 64*LDH)*2 };
    const unsigned u_rel   = smb + OFF_REL*2;
    __half* wpsH = smh + OFF_SCR + warp*16*LPSH;

    const int rsel = (lane & 7) + ((lane >> 3) & 1)*8;
    const int csel = (lane >> 4) * 8;

#pragma unroll
    for (int j = 0; j < 4; j++) {
        int c = tid + j*128, row = c >> 3, c16 = c & 7;
        cpa16(u_kb[0] + (unsigned)(row*LDH + c16*8)*2,
              g_kh + base + (size_t)row*HD + c16*8);
        cpa16(u_vb[0] + (unsigned)(row*LDH + c16*8)*2,
              g_vh + base + (size_t)row*HD + c16*8);
    }
    cpa_commit();

    int B = (n0 + 1089) % 192;
    for (int e = tid; e < 128*16; e += 128) {
        int r = e >> 4, c4 = (e & 15) << 2;
        int uu = n0 + r - 63;
        int dd = uu < -MAXPOS ? -MAXPOS : (uu > MAXPOS ? MAXPOS : uu);
        int rr = B + r; if (rr >= RELR) rr -= RELR;
        *(uint2*)(smh + OFF_REL + rr*LDH + c4) =
            *(const uint2*)(g_relh + (size_t)(dd+MAXPOS)*HD + c4);
    }
    for (int e = tid; e < 64*16; e += 128) {
        int m = e >> 4, c4 = (e & 15) << 2;
        *(uint2*)(smh + 64*LDH + m*LDH + c4) =
            *(const uint2*)(g_qh + base + (size_t)(n0+m)*HD + c4);
    }
    __syncthreads();

    unsigned qa[4][4];
#pragma unroll
    for (int ks = 0; ks < 4; ks++)
        ldsm4(qa[ks][0], qa[ks][1], qa[ks][2], qa[ks][3],
              u_kb[1] + (unsigned)((warp*16 + rsel)*LDH + ks*16 + csel)*2);

    float poslo0 = 0.f, poslo1 = 0.f, poshi0 = 0.f, poshi1 = 0.f;
    {
        const __half2* q0p = (const __half2*)(smh + 64*LDH + (warp*16 + lq    )*LDH);
        const __half2* q1p = (const __half2*)(smh + 64*LDH + (warp*16 + lq + 8)*LDH);
        const __half2* rl  = (const __half2*)(g_relh);
        const __half2* rh  = (const __half2*)(g_relh + (size_t)1024*HD);
#pragma unroll
        for (int kk = 0; kk < 32; kk++) {
            float2 q0 = __half22float2(q0p[kk]);
            float2 q1 = __half22float2(q1p[kk]);
            float2 a0 = __half22float2(rl[kk]);
            float2 a1 = __half22float2(rh[kk]);
            poslo0 += q0.x*a0.x + q0.y*a0.y;
            poshi0 += q0.x*a1.x + q0.y*a1.y;
            poslo1 += q1.x*a0.x + q1.y*a0.y;
            poshi1 += q1.x*a1.x + q1.y*a1.y;
        }
    }
    __syncthreads();

    float o[8][4];
#pragma unroll
    for (int i = 0; i < 8; i++)
#pragma unroll
        for (int j = 0; j < 4; j++) o[i][j] = 0.f;
    float li0 = 0.f, li1 = 0.f;

    for (int it = 0; it < 16; it++) {
        const int buf = it & 1;
        asm volatile("cp.async.wait_group 0;");
        __syncthreads();
        if (it < 15) {
            const int m0n = (it+1)*64;
            const int dn  = n0 - m0n;
            int Bn_ = B - 64; if (Bn_ < 0) Bn_ += RELR;
#pragma unroll
            for (int j = 0; j < 4; j++) {
                int c = tid + j*128, row = c >> 3, c16 = c & 7;
                cpa16(u_kb[buf^1] + (unsigned)(row*LDH + c16*8)*2,
                      g_kh + base + (size_t)(m0n+row)*HD + c16*8);
                cpa16(u_vb[buf^1] + (unsigned)(row*LDH + c16*8)*2,
                      g_vh + base + (size_t)(m0n+row)*HD + c16*8);
                int uu = dn + row - 63;
                int dd = uu < -MAXPOS ? -MAXPOS : (uu > MAXPOS ? MAXPOS : uu);
                int rr = Bn_ + row; if (rr >= RELR) rr -= RELR;
                cpa16(u_rel + (unsigned)(rr*LDH + c16*8)*2,
                      g_relh + (size_t)(dd+MAXPOS)*HD + c16*8);
            }
            cpa_commit();
        }

        float sc[8][4];
#pragma unroll
        for (int i = 0; i < 8; i++)
#pragma unroll
            for (int j = 0; j < 4; j++) sc[i][j] = 0.f;
#pragma unroll
        for (int ks = 0; ks < 4; ks++) {
#pragma unroll
            for (int cp = 0; cp < 4; cp++) {
                unsigned b0, b1, b2, b3;
                ldsm4(b0, b1, b2, b3,
                      u_kb[buf] + (unsigned)((cp*16 + rsel)*LDH + ks*16 + csel)*2);
                mma16(sc[2*cp  ], qa[ks][0],qa[ks][1],qa[ks][2],qa[ks][3], b0, b2);
                mma16(sc[2*cp+1], qa[ks][0],qa[ks][1],qa[ks][2],qa[ks][3], b1, b3);
            }
        }

        const int delta0c = n0 - it*64;
        const bool clipLow  = (delta0c <= -576);
        const bool clipHigh = (delta0c >=  576);

        if (!clipLow && !clipHigh) {
#pragma unroll
            for (int p = 0; p < 5; p++) {
                float pp0[4] = {0.f,0.f,0.f,0.f}, pp1[4] = {0.f,0.f,0.f,0.f};
                int rrow = B + warp*16 + p*16 + rsel;
                if (rrow >= RELR) rrow -= RELR;
#pragma unroll
                for (int ks = 0; ks < 4; ks++) {
                    unsigned b0, b1, b2, b3;
                    ldsm4(b0, b1, b2, b3,
                          u_rel + (unsigned)(rrow*LDH + ks*16 + csel)*2);
                    mma16(pp0, qa[ks][0],qa[ks][1],qa[ks][2],qa[ks][3], b0, b2);
                    mma16(pp1, qa[ks][0],qa[ks][1],qa[ks][2],qa[ks][3], b1, b3);
                }
                int c = 16*p + 2*lr;
                *(__half2*)(wpsH +  lq   *LPSH + c)     = __floats2half2_rn(pp0[0], pp0[1]);
                *(__half2*)(wpsH + (lq+8)*LPSH + c)     = __floats2half2_rn(pp0[2], pp0[3]);
                *(__half2*)(wpsH +  lq   *LPSH + c + 8) = __floats2half2_rn(pp1[0], pp1[1]);
                *(__half2*)(wpsH + (lq+8)*LPSH + c + 8) = __floats2half2_rn(pp1[2], pp1[3]);
            }
            __syncwarp();

#pragma unroll
            for (int ct = 0; ct < 8; ct++)
#pragma unroll
                for (int c = 0; c < 2; c++) {
                    int m  = ct*8 + 2*lr + c;
                    int u0 = lq - m + 63;
                    sc[ct][c]   += __half2float(wpsH[ lq   *LPSH + u0    ]);
                    sc[ct][2+c] += __half2float(wpsH[(lq+8)*LPSH + u0 + 8]);
                }
        } else {
            const float pc0 = clipLow ? poslo0 : poshi0;
            const float pc1 = clipLow ? poslo1 : poshi1;
#pragma unroll
            for (int ct = 0; ct < 8; ct++)
#pragma unroll
                for (int c = 0; c < 2; c++) {
                    sc[ct][c]   += pc0;
                    sc[ct][2+c] += pc1;
                }
        }

        unsigned pk[8][2];
#pragma unroll
        for (int ct = 0; ct < 8; ct++) {
            float p00 = ex2f(fmaf(sc[ct][0], EXSC, EXBI));
            float p01 = ex2f(fmaf(sc[ct][1], EXSC, EXBI));
            float p10 = ex2f(fmaf(sc[ct][2], EXSC, EXBI));
            float p11 = ex2f(fmaf(sc[ct][3], EXSC, EXBI));
            li0 += p00 + p01; li1 += p10 + p11;
            pk[ct][0] = h2u(p00, p01);
            pk[ct][1] = h2u(p10, p11);
        }

#pragma unroll
        for (int ks = 0; ks < 4; ks++) {
            unsigned a0 = pk[2*ks][0],   a1 = pk[2*ks][1];
            unsigned a2 = pk[2*ks+1][0], a3 = pk[2*ks+1][1];
            const int vrow = ks*16 + rsel;
#pragma unroll
            for (int s = 0; s < 4; s++) {
                unsigned r0, r1, r2, r3;
                ldsm4t(r0, r1, r2, r3,
                       u_vb[buf] + (unsigned)(vrow*LDH + s*16 + csel)*2);
                mma16(o[2*s  ], a0, a1, a2, a3, r0, r1);
                mma16(o[2*s+1], a0, a1, a2, a3, r2, r3);
            }
        }

        B -= 64; if (B < 0) B += RELR;
    }

    li0 += __shfl_xor_sync(~0u, li0, 1); li0 += __shfl_xor_sync(~0u, li0, 2);
    li1 += __shfl_xor_sync(~0u, li1, 1); li1 += __shfl_xor_sync(~0u, li1, 2);

    const float inv0 = 1.f / li0, inv1 = 1.f / li1;
    const int b_ = bh >> 3, h_ = bh & 7;
#pragma unroll
    for (int ct = 0; ct < 8; ct++) {
        int col = h_*HD + ct*8 + 2*lr;
        int r0  = n0 + warp*16 + lq;
        *(__half2*)(g_atth + ((size_t)(b_*Tn + r0    )*OUTD + col)) =
            __floats2half2_rn(o[ct][0]*inv0, o[ct][1]*inv0);
        *(__half2*)(g_atth + ((size_t)(b_*Tn + r0 + 8)*OUTD + col)) =
            __floats2half2_rn(o[ct][2]*inv1, o[ct][3]*inv1);
    }
}

// ============================================================
extern "C" void kernel_launch(void* const* d_in, const int* in_sizes, int n_in,
                              void* d_out, int out_size)
{
    const float* x    = (const float*)d_in[0];
    const float* Wq   = (const float*)d_in[1];
    const float* bq   = (const float*)d_in[2];
    const float* Wkv  = (const float*)d_in[3];
    const float* bkv  = (const float*)d_in[4];
    const float* Wout = (const float*)d_in[5];
    const float* bout = (const float*)d_in[6];
    const float* rel  = (const float*)d_in[7];
    float* out = (float*)d_out;

    cudaFuncSetAttribute(attn_mma,
                         cudaFuncAttributeMaxDynamicSharedMemorySize, ATTN_SMEM);
    cudaFuncSetAttribute(qkv_mma,
                         cudaFuncAttributeMaxDynamicSharedMemorySize, GEMM_SMEM);
    cudaFuncSetAttribute(out_mma,
                         cudaFuncAttributeMaxDynamicSharedMemorySize, GEMM_SMEM);

    conv_all<<<NCONVB, 256>>>(x, rel, Wq, Wkv, Wout);

    // QKV: 1536/64 = 24 col-tiles, 8192/128 = 64 row-tiles
    qkv_mma<<<dim3(24, 64), 256, GEMM_SMEM>>>(bq, bkv);
    attn_mma<<<dim3(16, 64), 128, ATTN_SMEM>>>();
    // out: 512/64 = 8 col-tiles
    out_mma<<<dim3(8, 64), 256, GEMM_SMEM>>>(bout, out);
}

// round 17
// speedup vs baseline: 1.0181x; 1.0181x over previous
#include <cuda_runtime.h>
#include <cuda_fp16.h>

#define Bn 8
#define Tn 1024
#define IND 512
#define NH 8
#define HD 64
#define OUTD 512
#define MAXPOS 512

// -------- scratch (allocations forbidden; device globals) --------
__device__ __half g_xh [(size_t)Bn*Tn*IND];
__device__ __half g_wqh[(size_t)OUTD*IND];        // [n][k]
__device__ __half g_wkvh[(size_t)2*OUTD*IND];     // [n][k]
__device__ __half g_wouth[(size_t)IND*OUTD];      // [n][k]
__device__ __half g_relh[(size_t)(2*MAXPOS+1)*HD];
__device__ __half g_qh[(size_t)Bn*NH*Tn*HD];
__device__ __half g_kh[(size_t)Bn*NH*Tn*HD];
__device__ __half g_vh[(size_t)Bn*NH*Tn*HD];
__device__ __half g_atth[(size_t)Bn*Tn*OUTD];

// -------- helpers --------
__device__ __forceinline__ void mma16(float* c,
    unsigned a0, unsigned a1, unsigned a2, unsigned a3,
    unsigned b0, unsigned b1)
{
    asm volatile(
      "mma.sync.aligned.m16n8k16.row.col.f32.f16.f16.f32 "
      "{%0,%1,%2,%3},{%4,%5,%6,%7},{%8,%9},{%0,%1,%2,%3};"
      : "+f"(c[0]), "+f"(c[1]), "+f"(c[2]), "+f"(c[3])
      : "r"(a0), "r"(a1), "r"(a2), "r"(a3), "r"(b0), "r"(b1));
}
__device__ __forceinline__ void cpa8(unsigned dst, const void* src) {
    asm volatile("cp.async.ca.shared.global [%0], [%1], 8;" :: "r"(dst), "l"(src));
}
__device__ __forceinline__ void cpa16(unsigned dst, const void* src) {
    asm volatile("cp.async.cg.shared.global [%0], [%1], 16;" :: "r"(dst), "l"(src));
}
__device__ __forceinline__ void cpa_commit() { asm volatile("cp.async.commit_group;"); }
__device__ __forceinline__ void ldsm4(unsigned &r0, unsigned &r1, unsigned &r2, unsigned &r3,
                                      unsigned addr)
{
    asm volatile("ldmatrix.sync.aligned.m8n8.x4.shared.b16 {%0,%1,%2,%3}, [%4];"
        : "=r"(r0), "=r"(r1), "=r"(r2), "=r"(r3) : "r"(addr));
}
__device__ __forceinline__ void ldsm4t(unsigned &r0, unsigned &r1, unsigned &r2, unsigned &r3,
                                       unsigned addr)
{
    asm volatile("ldmatrix.sync.aligned.m8n8.x4.trans.shared.b16 {%0,%1,%2,%3}, [%4];"
        : "=r"(r0), "=r"(r1), "=r"(r2), "=r"(r3) : "r"(addr));
}
__device__ __forceinline__ float ex2f(float x) {
    float r; asm("ex2.approx.ftz.f32 %0, %1;" : "=f"(r) : "f"(x)); return r;
}
__device__ __forceinline__ unsigned h2u(float a, float b) {
    __half2 h = __floats2half2_rn(a, b);
    return *(unsigned*)&h;
}
#define EXSC 0.1803368809f
#define EXBI (-5.7707801636f)

// ============================================================
// conversion: flat blocks (x, rel) + tiled transpose blocks (W).
// ============================================================
#define NX (Bn*Tn*IND/4)
#define NR ((2*MAXPOS+1)*HD/4)
#define FLATB ((NX + NR + 255)/256)
#define TQ 64
#define TKV 128
#define TO 64
__global__ void conv_all(const float* __restrict__ x, const float* __restrict__ rel,
                         const float* __restrict__ Wq, const float* __restrict__ Wkv,
                         const float* __restrict__ Wout)
{
    const int b = blockIdx.x;
    const int t = threadIdx.x;
    if (b < FLATB) {
        int i = b*256 + t;
        if (i < NX) {
            float4 v = *(const float4*)(x + 4*(size_t)i);
            *(__half2*)(g_xh + 4*(size_t)i)     = __floats2half2_rn(v.x, v.y);
            *(__half2*)(g_xh + 4*(size_t)i + 2) = __floats2half2_rn(v.z, v.w);
        } else if (i < NX + NR) {
            int j = i - NX;
            float4 v = *(const float4*)(rel + 4*(size_t)j);
            *(__half2*)(g_relh + 4*(size_t)j)     = __floats2half2_rn(v.x, v.y);
            *(__half2*)(g_relh + 4*(size_t)j + 2) = __floats2half2_rn(v.z, v.w);
        }
        return;
    }
    int tb = b - FLATB;
    const float* src; __half* dst; int N, ncols_t;
    if (tb < TQ)            { src = Wq;   dst = g_wqh;   N = 512;  ncols_t = 8;  }
    else if (tb < TQ+TKV)   { tb -= TQ;   src = Wkv;  dst = g_wkvh;  N = 1024; ncols_t = 16; }
    else                    { tb -= TQ+TKV; src = Wout; dst = g_wouth; N = 512; ncols_t = 8; }
    const int k0 = (tb / ncols_t) * 64;
    const int n0 = (tb % ncols_t) * 64;

    __shared__ float s[64][65];
    {
        int r = t >> 2, cq = t & 3;
        const float* rp = src + (size_t)(k0 + r)*N + n0;
#pragma unroll
        for (int j = 0; j < 4; j++) {
            float4 v = *(const float4*)(rp + (cq + j*4)*4);
            s[r][(cq + j*4)*4 + 0] = v.x;
            s[r][(cq + j*4)*4 + 1] = v.y;
            s[r][(cq + j*4)*4 + 2] = v.z;
            s[r][(cq + j*4)*4 + 3] = v.w;
        }
    }
    __syncthreads();
    {
        int n = t >> 2, ks = (t & 3) * 16;
        __half* wp = dst + (size_t)(n0 + n)*512 + k0 + ks;
        __half hv[16];
#pragma unroll
        for (int j = 0; j < 16; j++)
            hv[j] = __float2half_rn(s[ks + j][n]);
        *(uint4*)(wp)     = *(uint4*)(hv);
        *(uint4*)(wp + 8) = *(uint4*)(hv + 8);
    }
}
#define NCONVB (FLATB + TQ + TKV + TO)

// ============================================================
// fp16 GEMM body: BM=128, BN=128, BK=32, 256 thr, FOUR-stage
// cp.async pipeline, ONE barrier per k-iter, ldmatrix fragments.
// smem = 4*2*10240 = 81,920 B -> 2 blocks/SM.
// ============================================================
#define LDS_S 40
#define GSTG_BYTES (128*LDS_S*2)
#define NSTG 4
#define GEMM_SMEM (NSTG*2*GSTG_BYTES)

#define GSTAGE(bufi, kn, APTR, LDA, BPTR)                                       \
    {                                                                           \
        const unsigned ao = (unsigned)(bufi) * GSTG_BYTES;                      \
        _Pragma("unroll")                                                       \
        for (int j = 0; j < 4; j++) {                                           \
            int c = tid + j*256, row = c >> 3, c4 = (c & 7) << 2;               \
            cpa8(sa_u + ao + row*(LDS_S*2) + c4*2,                              \
                 (APTR) + (size_t)(row0 + row)*(LDA) + (kn) + c4);              \
            cpa8(sb_u + ao + row*(LDS_S*2) + c4*2,                              \
                 (BPTR) + (size_t)row*IND + (kn) + c4);                         \
        }                                                                       \
        cpa_commit();                                                           \
    }

#define HGEMM(APTR, LDA, BPTR)                                                  \
    extern __shared__ __half smg[];                                             \
    __half* s_a = smg;                                                          \
    __half* s_b = smg + NSTG*128*LDS_S;                                         \
    const int tid = threadIdx.x, lane = tid & 31, warp = tid >> 5;              \
    const int wr = warp & 3, wc = warp >> 2;                                    \
    const int lq = lane >> 2, lr = lane & 3;                                    \
    const int rsel = (lane & 7) + ((lane >> 3) & 1)*8;                          \
    const int csel = (lane >> 4)*8;                                             \
    unsigned sa_u = (unsigned)__cvta_generic_to_shared(s_a);                    \
    unsigned sb_u = (unsigned)__cvta_generic_to_shared(s_b);                    \
    float acc[2][8][4];                                                         \
    _Pragma("unroll") for (int i = 0; i < 2; i++)                               \
    _Pragma("unroll") for (int j = 0; j < 8; j++)                               \
    _Pragma("unroll") for (int e = 0; e < 4; e++) acc[i][j][e] = 0.f;           \
    GSTAGE(0, 0,  APTR, LDA, BPTR)                                              \
    GSTAGE(1, 32, APTR, LDA, BPTR)                                              \
    GSTAGE(2, 64, APTR, LDA, BPTR)                                              \
    int bufc = 0, bufs = 3;                                                     \
    for (int it = 0; it < 16; it++) {                                           \
        if (it < 14)      asm volatile("cp.async.wait_group 2;");               \
        else if (it < 15) asm volatile("cp.async.wait_group 1;");               \
        else              asm volatile("cp.async.wait_group 0;");               \
        __syncthreads();                                                        \
        if (it < 13) GSTAGE(bufs, (it+3) << 5, APTR, LDA, BPTR)                 \
        const unsigned pa_u = sa_u + (unsigned)bufc*GSTG_BYTES;                 \
        const unsigned pb_u = sb_u + (unsigned)bufc*GSTG_BYTES;                 \
        _Pragma("unroll")                                                       \
        for (int ks = 0; ks < 2; ks++) {                                        \
            unsigned a[2][4];                                                   \
            _Pragma("unroll")                                                   \
            for (int rt = 0; rt < 2; rt++)                                      \
                ldsm4(a[rt][0], a[rt][1], a[rt][2], a[rt][3],                   \
                      pa_u + (unsigned)((wr*32 + rt*16 + rsel)*LDS_S            \
                                        + ks*16 + csel)*2);                     \
            _Pragma("unroll")                                                   \
            for (int cp = 0; cp < 4; cp++) {                                    \
                unsigned b0, b1, b2, b3;                                        \
                ldsm4(b0, b1, b2, b3,                                           \
                      pb_u + (unsigned)((wc*64 + cp*16 + rsel)*LDS_S            \
                                        + ks*16 + csel)*2);                     \
                _Pragma("unroll")                                               \
                for (int rt = 0; rt < 2; rt++) {                                \
                    mma16(acc[rt][2*cp  ], a[rt][0],a[rt][1],a[rt][2],a[rt][3], \
                          b0, b2);                                              \
                    mma16(acc[rt][2*cp+1], a[rt][0],a[rt][1],a[rt][2],a[rt][3], \
                          b1, b3);                                              \
                }                                                               \
            }                                                                   \
        }                                                                       \
        bufc = (bufc == NSTG-1) ? 0 : bufc + 1;                                 \
        bufs = (bufs == NSTG-1) ? 0 : bufs + 1;                                 \
    }

// ============================================================
// Kernel 1: QKV projection (fp16)
// ============================================================
__global__ __launch_bounds__(256) void qkv_mma(
    const float* __restrict__ bq, const float* __restrict__ bkv)
{
    const int row0 = blockIdx.y * 128, col0 = blockIdx.x * 128;
    const __half* Bp; const float* bias;
    if (col0 < OUTD) { Bp = g_wqh  + (size_t)col0*IND;         bias = bq  + col0; }
    else             { Bp = g_wkvh + (size_t)(col0-OUTD)*IND;  bias = bkv + (col0-OUTD); }

    HGEMM(g_xh, IND, Bp)

    const int seg = col0 >> 9;
    __half* dst = (seg == 0) ? g_qh : (seg == 1) ? g_kh : g_vh;
    const int h = ((col0 & 511) >> 6) + wc;

#pragma unroll
    for (int rt = 0; rt < 2; rt++)
#pragma unroll
        for (int ct = 0; ct < 8; ct++)
#pragma unroll
            for (int hh = 0; hh < 2; hh++) {
                int r  = row0 + wr*32 + rt*16 + lq + 8*hh;
                int bb = r >> 10, tt = r & 1023;
                int colL = wc*64 + ct*8 + 2*lr;
                int d    = ct*8 + 2*lr;
                __half2 w = __floats2half2_rn(acc[rt][ct][2*hh+0] + bias[colL],
                                              acc[rt][ct][2*hh+1] + bias[colL+1]);
                *(__half2*)(dst + ((size_t)(bb*NH + h)*Tn + tt)*HD + d) = w;
            }
}

// ============================================================
// Kernel 3: output projection (fp16 -> fp32 out)
// ============================================================
__global__ __launch_bounds__(256) void out_mma(
    const float* __restrict__ bout, float* __restrict__ out)
{
    const int row0 = blockIdx.y * 128, col0 = blockIdx.x * 128;
    const __half* Bp = g_wouth + (size_t)col0*OUTD;

    HGEMM(g_atth, OUTD, Bp)

#pragma unroll
    for (int rt = 0; rt < 2; rt++)
#pragma unroll
        for (int ct = 0; ct < 8; ct++)
#pragma unroll
            for (int hh = 0; hh < 2; hh++) {
                int r    = row0 + wr*32 + rt*16 + lq + 8*hh;
                int colL = wc*64 + ct*8 + 2*lr;
                float2 w;
                w.x = acc[rt][ct][2*hh+0] + bout[col0 + colL];
                w.y = acc[rt][ct][2*hh+1] + bout[col0 + colL+1];
                *(float2*)(out + (size_t)r * IND + col0 + colL) = w;
            }
}

// ============================================================
// Kernel 2: attention — unchanged from committed R14/R15.
// ============================================================
#define LDH 72
#define RELR 192
#define LPSH 88
#define OFF_V   9216
#define OFF_REL 18432
#define OFF_SCR 32256
#define ATTN_SMEM (37888*2)     // 75,776 B

__global__ __launch_bounds__(128, 3) void attn_mma()
{
    extern __shared__ __half smh[];
    const int tid = threadIdx.x, lane = tid & 31, warp = tid >> 5;
    const int lq = lane >> 2, lr = lane & 3;
    const int bx = blockIdx.x;
    const int ntile = (bx & 1) ? (7 - (bx >> 1)) : (8 + (bx >> 1));
    const int n0 = ntile * 64;
    const int bh = blockIdx.y;
    const size_t base = (size_t)bh * Tn * HD;

    const unsigned smb = (unsigned)__cvta_generic_to_shared(smh);
    const unsigned u_kb[2] = { smb, smb + 64*LDH*2 };
    const unsigned u_vb[2] = { smb + OFF_V*2, smb + (OFF_V + 64*LDH)*2 };
    const unsigned u_rel   = smb + OFF_REL*2;
    __half* wpsH = smh + OFF_SCR + warp*16*LPSH;

    const int rsel = (lane & 7) + ((lane >> 3) & 1)*8;
    const int csel = (lane >> 4) * 8;

#pragma unroll
    for (int j = 0; j < 4; j++) {
        int c = tid + j*128, row = c >> 3, c16 = c & 7;
        cpa16(u_kb[0] + (unsigned)(row*LDH + c16*8)*2,
              g_kh + base + (size_t)row*HD + c16*8);
        cpa16(u_vb[0] + (unsigned)(row*LDH + c16*8)*2,
              g_vh + base + (size_t)row*HD + c16*8);
    }
    cpa_commit();

    int B = (n0 + 1089) % 192;
    for (int e = tid; e < 128*16; e += 128) {
        int r = e >> 4, c4 = (e & 15) << 2;
        int uu = n0 + r - 63;
        int dd = uu < -MAXPOS ? -MAXPOS : (uu > MAXPOS ? MAXPOS : uu);
        int rr = B + r; if (rr >= RELR) rr -= RELR;
        *(uint2*)(smh + OFF_REL + rr*LDH + c4) =
            *(const uint2*)(g_relh + (size_t)(dd+MAXPOS)*HD + c4);
    }
    for (int e = tid; e < 64*16; e += 128) {
        int m = e >> 4, c4 = (e & 15) << 2;
        *(uint2*)(smh + 64*LDH + m*LDH + c4) =
            *(const uint2*)(g_qh + base + (size_t)(n0+m)*HD + c4);
    }
    __syncthreads();

    unsigned qa[4][4];
#pragma unroll
    for (int ks = 0; ks < 4; ks++)
        ldsm4(qa[ks][0], qa[ks][1], qa[ks][2], qa[ks][3],
              u_kb[1] + (unsigned)((warp*16 + rsel)*LDH + ks*16 + csel)*2);

    float poslo0 = 0.f, poslo1 = 0.f, poshi0 = 0.f, poshi1 = 0.f;
    {
        const __half2* q0p = (const __half2*)(smh + 64*LDH + (warp*16 + lq    )*LDH);
        const __half2* q1p = (const __half2*)(smh + 64*LDH + (warp*16 + lq + 8)*LDH);
        const __half2* rl  = (const __half2*)(g_relh);
        const __half2* rh  = (const __half2*)(g_relh + (size_t)1024*HD);
#pragma unroll
        for (int kk = 0; kk < 32; kk++) {
            float2 q0 = __half22float2(q0p[kk]);
            float2 q1 = __half22float2(q1p[kk]);
            float2 a0 = __half22float2(rl[kk]);
            float2 a1 = __half22float2(rh[kk]);
            poslo0 += q0.x*a0.x + q0.y*a0.y;
            poshi0 += q0.x*a1.x + q0.y*a1.y;
            poslo1 += q1.x*a0.x + q1.y*a0.y;
            poshi1 += q1.x*a1.x + q1.y*a1.y;
        }
    }
    __syncthreads();

    float o[8][4];
#pragma unroll
    for (int i = 0; i < 8; i++)
#pragma unroll
        for (int j = 0; j < 4; j++) o[i][j] = 0.f;
    float li0 = 0.f, li1 = 0.f;

    for (int it = 0; it < 16; it++) {
        const int buf = it & 1;
        asm volatile("cp.async.wait_group 0;");
        __syncthreads();
        if (it < 15) {
            const int m0n = (it+1)*64;
            const int dn  = n0 - m0n;
            int Bn_ = B - 64; if (Bn_ < 0) Bn_ += RELR;
#pragma unroll
            for (int j = 0; j < 4; j++) {
                int c = tid + j*128, row = c >> 3, c16 = c & 7;
                cpa16(u_kb[buf^1] + (unsigned)(row*LDH + c16*8)*2,
                      g_kh + base + (size_t)(m0n+row)*HD + c16*8);
                cpa16(u_vb[buf^1] + (unsigned)(row*LDH + c16*8)*2,
                      g_vh + base + (size_t)(m0n+row)*HD + c16*8);
                int uu = dn + row - 63;
                int dd = uu < -MAXPOS ? -MAXPOS : (uu > MAXPOS ? MAXPOS : uu);
                int rr = Bn_ + row; if (rr >= RELR) rr -= RELR;
                cpa16(u_rel + (unsigned)(rr*LDH + c16*8)*2,
                      g_relh + (size_t)(dd+MAXPOS)*HD + c16*8);
            }
            cpa_commit();
        }

        float sc[8][4];
#pragma unroll
        for (int i = 0; i < 8; i++)
#pragma unroll
            for (int j = 0; j < 4; j++) sc[i][j] = 0.f;
#pragma unroll
        for (int ks = 0; ks < 4; ks++) {
#pragma unroll
            for (int cp = 0; cp < 4; cp++) {
                unsigned b0, b1, b2, b3;
                ldsm4(b0, b1, b2, b3,
                      u_kb[buf] + (unsigned)((cp*16 + rsel)*LDH + ks*16 + csel)*2);
                mma16(sc[2*cp  ], qa[ks][0],qa[ks][1],qa[ks][2],qa[ks][3], b0, b2);
                mma16(sc[2*cp+1], qa[ks][0],qa[ks][1],qa[ks][2],qa[ks][3], b1, b3);
            }
        }

        const int delta0c = n0 - it*64;
        const bool clipLow  = (delta0c <= -576);
        const bool clipHigh = (delta0c >=  576);

        if (!clipLow && !clipHigh) {
#pragma unroll
            for (int p = 0; p < 5; p++) {
                float pp0[4] = {0.f,0.f,0.f,0.f}, pp1[4] = {0.f,0.f,0.f,0.f};
                int rrow = B + warp*16 + p*16 + rsel;
                if (rrow >= RELR) rrow -= RELR;
#pragma unroll
                for (int ks = 0; ks < 4; ks++) {
                    unsigned b0, b1, b2, b3;
                    ldsm4(b0, b1, b2, b3,
                          u_rel + (unsigned)(rrow*LDH + ks*16 + csel)*2);
                    mma16(pp0, qa[ks][0],qa[ks][1],qa[ks][2],qa[ks][3], b0, b2);
                    mma16(pp1, qa[ks][0],qa[ks][1],qa[ks][2],qa[ks][3], b1, b3);
                }
                int c = 16*p + 2*lr;
                *(__half2*)(wpsH +  lq   *LPSH + c)     = __floats2half2_rn(pp0[0], pp0[1]);
                *(__half2*)(wpsH + (lq+8)*LPSH + c)     = __floats2half2_rn(pp0[2], pp0[3]);
                *(__half2*)(wpsH +  lq   *LPSH + c + 8) = __floats2half2_rn(pp1[0], pp1[1]);
                *(__half2*)(wpsH + (lq+8)*LPSH + c + 8) = __floats2half2_rn(pp1[2], pp1[3]);
            }
            __syncwarp();

#pragma unroll
            for (int ct = 0; ct < 8; ct++)
#pragma unroll
                for (int c = 0; c < 2; c++) {
                    int m  = ct*8 + 2*lr + c;
                    int u0 = lq - m + 63;
                    sc[ct][c]   += __half2float(wpsH[ lq   *LPSH + u0    ]);
                    sc[ct][2+c] += __half2float(wpsH[(lq+8)*LPSH + u0 + 8]);
                }
        } else {
            const float pc0 = clipLow ? poslo0 : poshi0;
            const float pc1 = clipLow ? poslo1 : poshi1;
#pragma unroll
            for (int ct = 0; ct < 8; ct++)
#pragma unroll
                for (int c = 0; c < 2; c++) {
                    sc[ct][c]   += pc0;
                    sc[ct][2+c] += pc1;
                }
        }

        unsigned pk[8][2];
#pragma unroll
        for (int ct = 0; ct < 8; ct++) {
            float p00 = ex2f(fmaf(sc[ct][0], EXSC, EXBI));
            float p01 = ex2f(fmaf(sc[ct][1], EXSC, EXBI));
            float p10 = ex2f(fmaf(sc[ct][2], EXSC, EXBI));
            float p11 = ex2f(fmaf(sc[ct][3], EXSC, EXBI));
            li0 += p00 + p01; li1 += p10 + p11;
            pk[ct][0] = h2u(p00, p01);
            pk[ct][1] = h2u(p10, p11);
        }

#pragma unroll
        for (int ks = 0; ks < 4; ks++) {
            unsigned a0 = pk[2*ks][0],   a1 = pk[2*ks][1];
            unsigned a2 = pk[2*ks+1][0], a3 = pk[2*ks+1][1];
            const int vrow = ks*16 + rsel;
#pragma unroll
            for (int s = 0; s < 4; s++) {
                unsigned r0, r1, r2, r3;
                ldsm4t(r0, r1, r2, r3,
                       u_vb[buf] + (unsigned)(vrow*LDH + s*16 + csel)*2);
                mma16(o[2*s  ], a0, a1, a2, a3, r0, r1);
                mma16(o[2*s+1], a0, a1, a2, a3, r2, r3);
            }
        }

        B -= 64; if (B < 0) B += RELR;
    }

    li0 += __shfl_xor_sync(~0u, li0, 1); li0 += __shfl_xor_sync(~0u, li0, 2);
    li1 += __shfl_xor_sync(~0u, li1, 1); li1 += __shfl_xor_sync(~0u, li1, 2);

    const float inv0 = 1.f / li0, inv1 = 1.f / li1;
    const int b_ = bh >> 3, h_ = bh & 7;
#pragma unroll
    for (int ct = 0; ct < 8; ct++) {
        int col = h_*HD + ct*8 + 2*lr;
        int r0  = n0 + warp*16 + lq;
        *(__half2*)(g_atth + ((size_t)(b_*Tn + r0    )*OUTD + col)) =
            __floats2half2_rn(o[ct][0]*inv0, o[ct][1]*inv0);
        *(__half2*)(g_atth + ((size_t)(b_*Tn + r0 + 8)*OUTD + col)) =
            __floats2half2_rn(o[ct][2]*inv1, o[ct][3]*inv1);
    }
}

// ============================================================
extern "C" void kernel_launch(void* const* d_in, const int* in_sizes, int n_in,
                              void* d_out, int out_size)
{
    const float* x    = (const float*)d_in[0];
    const float* Wq   = (const float*)d_in[1];
    const float* bq   = (const float*)d_in[2];
    const float* Wkv  = (const float*)d_in[3];
    const float* bkv  = (const float*)d_in[4];
    const float* Wout = (const float*)d_in[5];
    const float* bout = (const float*)d_in[6];
    const float* rel  = (const float*)d_in[7];
    float* out = (float*)d_out;

    cudaFuncSetAttribute(attn_mma,
                         cudaFuncAttributeMaxDynamicSharedMemorySize, ATTN_SMEM);
    cudaFuncSetAttribute(qkv_mma,
                         cudaFuncAttributeMaxDynamicSharedMemorySize, GEMM_SMEM);
    cudaFuncSetAttribute(out_mma,
                         cudaFuncAttributeMaxDynamicSharedMemorySize, GEMM_SMEM);

    conv_all<<<NCONVB, 256>>>(x, rel, Wq, Wkv, Wout);

    qkv_mma<<<dim3(12, 64), 256, GEMM_SMEM>>>(bq, bkv);
    attn_mma<<<dim3(16, 64), 128, ATTN_SMEM>>>();
    out_mma<<<dim3(4, 64), 256, GEMM_SMEM>>>(bout, out);
}